// round 4
// baseline (speedup 1.0000x reference)
#include <cuda_runtime.h>

#define BB 2
#define NN 65536
#define CCH 128
#define ZYX (64*64*64)
#define TP 1217
#define WSTRIDE 1220
#define BLOCK 256

__device__ float g_ct[(size_t)BB * ZYX * CCH]; // c_plane transposed to [B, ZYX, C]

__device__ __forceinline__ float leakyf(float v) { return v >= 0.0f ? v : 0.01f * v; }

__device__ __forceinline__ float src_idx(float v) {
    float g = fminf(fmaxf((2.0f * v) / 63.0f - 1.0f, -2.0f), 2.0f);
    return fminf(fmaxf((g + 1.0f) * 0.5f * 63.0f, 0.0f), 63.0f);
}

__device__ __forceinline__ float4 lerp4(float4 a, float4 b, float w, float omw) {
    float4 r;
    r.x = a.x * omw + b.x * w;  r.y = a.y * omw + b.y * w;
    r.z = a.z * omw + b.z * w;  r.w = a.w * omw + b.w * w;
    return r;
}

// [B, C, ZYX] -> [B, ZYX, C]
__global__ void transpose_kernel(const float* __restrict__ in) {
    __shared__ float tile[32][33];
    int b = blockIdx.z, s0 = blockIdx.x * 32, c0 = blockIdx.y * 32;
    const float* ib = in   + (size_t)b * CCH * ZYX;
    float*       ob = g_ct + (size_t)b * ZYX * CCH;
    int tx = threadIdx.x, ty = threadIdx.y;
#pragma unroll
    for (int j = 0; j < 32; j += 8)
        tile[ty + j][tx] = ib[(size_t)(c0 + ty + j) * ZYX + s0 + tx];
    __syncthreads();
#pragma unroll
    for (int j = 0; j < 32; j += 8)
        ob[(size_t)(s0 + ty + j) * CCH + c0 + tx] = tile[tx][ty + j];
}

__global__ __launch_bounds__(BLOCK, 1)
void fused_decoder_kernel(const float* __restrict__ pm,
                          const float* __restrict__ Wh1,
                          const float* __restrict__ bh1,
                          const float* __restrict__ Wh2,
                          const float* __restrict__ bh2,
                          const float* __restrict__ Wh3,
                          const float* __restrict__ bh3,
                          float* __restrict__ out_scalar,
                          float* __restrict__ out_feats)
{
    extern __shared__ float sm[];
    float* Wh3s = sm;                    // 32*WSTRIDE
    float* Wh1s = Wh3s + 32 * WSTRIDE;   // 4096
    float* Wh2s = Wh1s + 4096;           // 1024
    float* bh3s = Wh2s + 1024;           // WSTRIDE
    float* bh1s = bh3s + WSTRIDE;        // 32
    float* bh2s = bh1s + 32;             // 32
    float* als  = bh2s + 32;             // 33*BLOCK

    const int tid = threadIdx.x;

    for (int i = tid; i < 32 * TP; i += BLOCK) {
        int k = i / TP, c = i - k * TP;
        Wh3s[k * WSTRIDE + c] = Wh3[i];
    }
    for (int i = tid; i < 4096; i += BLOCK) Wh1s[i] = Wh1[i];
    for (int i = tid; i < 1024; i += BLOCK) Wh2s[i] = Wh2[i];
    for (int i = tid; i < TP;   i += BLOCK) bh3s[i] = bh3[i];
    if (tid < 32) { bh1s[tid] = bh1[tid]; bh2s[tid] = bh2[tid]; }
    __syncthreads();

    const int stride = gridDim.x * BLOCK;
    for (int p = blockIdx.x * BLOCK + tid; p < BB * NN; p += stride) {
        const float vx = pm[3 * p + 0];
        const float vy = pm[3 * p + 1];
        const float vz = pm[3 * p + 2];

        float ix = src_idx(vx), iy = src_idx(vy), iz = src_idx(vz);
        float fx = floorf(ix), fy = floorf(iy), fz = floorf(iz);
        float wx = ix - fx, wy = iy - fy, wz = iz - fz;
        int x0 = min(max((int)fx, 0), 63); int x1 = min(x0 + 1, 63);
        int y0 = min(max((int)fy, 0), 63); int y1 = min(y0 + 1, 63);
        int z0 = min(max((int)fz, 0), 63); int z1 = min(z0 + 1, 63);

        const int b = p >> 16;
        const float* cb = g_ct + (size_t)b * ZYX * CCH;
        const float4* q000 = (const float4*)(cb + (size_t)((z0 * 64 + y0) * 64 + x0) * CCH);
        const float4* q001 = (const float4*)(cb + (size_t)((z0 * 64 + y0) * 64 + x1) * CCH);
        const float4* q010 = (const float4*)(cb + (size_t)((z0 * 64 + y1) * 64 + x0) * CCH);
        const float4* q011 = (const float4*)(cb + (size_t)((z0 * 64 + y1) * 64 + x1) * CCH);
        const float4* q100 = (const float4*)(cb + (size_t)((z1 * 64 + y0) * 64 + x0) * CCH);
        const float4* q101 = (const float4*)(cb + (size_t)((z1 * 64 + y0) * 64 + x1) * CCH);
        const float4* q110 = (const float4*)(cb + (size_t)((z1 * 64 + y1) * 64 + x0) * CCH);
        const float4* q111 = (const float4*)(cb + (size_t)((z1 * 64 + y1) * 64 + x1) * CCH);

        const float omx = 1.0f - wx, omy = 1.0f - wy, omz = 1.0f - wz;

        float h1[32];
#pragma unroll
        for (int j = 0; j < 32; j++) h1[j] = 0.0f;

        float4* fo = (float4*)(out_feats + (size_t)p * CCH);

        // gather + trilinear + feats store + feats@Wh1
#pragma unroll 2
        for (int cc = 0; cc < 32; ++cc) {
            float4 a000 = q000[cc], a001 = q001[cc];
            float4 a010 = q010[cc], a011 = q011[cc];
            float4 a100 = q100[cc], a101 = q101[cc];
            float4 a110 = q110[cc], a111 = q111[cc];

            float4 c00 = lerp4(a000, a001, wx, omx);
            float4 c01 = lerp4(a010, a011, wx, omx);
            float4 c10 = lerp4(a100, a101, wx, omx);
            float4 c11 = lerp4(a110, a111, wx, omx);
            float4 c0  = lerp4(c00, c01, wy, omy);
            float4 c1  = lerp4(c10, c11, wy, omy);
            float4 f   = lerp4(c0, c1, wz, omz);

            fo[cc] = f;

            float fa[4] = { f.x, f.y, f.z, f.w };
#pragma unroll
            for (int e = 0; e < 4; e++) {
                float fc = fa[e];
                const float4* wr = (const float4*)(Wh1s + (cc * 4 + e) * 32);
#pragma unroll
                for (int m = 0; m < 8; m++) {
                    float4 w = wr[m];
                    h1[4*m+0] += fc * w.x; h1[4*m+1] += fc * w.y;
                    h1[4*m+2] += fc * w.z; h1[4*m+3] += fc * w.w;
                }
            }
        }

#pragma unroll
        for (int j = 0; j < 32; j++) h1[j] = leakyf(h1[j] + bh1s[j]);

        float h2[32];
#pragma unroll
        for (int j = 0; j < 32; j++) h2[j] = 0.0f;
#pragma unroll
        for (int k = 0; k < 32; k++) {
            float hk = h1[k];
            const float4* wr = (const float4*)(Wh2s + k * 32);
#pragma unroll
            for (int m = 0; m < 8; m++) {
                float4 w = wr[m];
                h2[4*m+0] += hk * w.x; h2[4*m+1] += hk * w.y;
                h2[4*m+2] += hk * w.z; h2[4*m+3] += hk * w.w;
            }
        }

        float hl[32];
#pragma unroll
        for (int j = 0; j < 32; j++) hl[j] = leakyf(h2[j] + bh2s[j]);

        // generated MLP layer 1
        const float xw0 = vx - truncf(vx) - 0.5f;
        const float xw1 = vy - truncf(vy) - 0.5f;
        const float xw2 = vz - truncf(vz) - 0.5f;

        float o1[32];
#pragma unroll
        for (int m = 0; m < 8; m++) {
            float4 b0 = ((const float4*)(bh3s +  0))[m];
            float4 b1 = ((const float4*)(bh3s + 32))[m];
            float4 b2 = ((const float4*)(bh3s + 64))[m];
            float4 b3 = ((const float4*)(bh3s + 96))[m];
            o1[4*m+0] = xw0*b0.x + xw1*b1.x + xw2*b2.x + b3.x;
            o1[4*m+1] = xw0*b0.y + xw1*b1.y + xw2*b2.y + b3.y;
            o1[4*m+2] = xw0*b0.z + xw1*b1.z + xw2*b2.z + b3.z;
            o1[4*m+3] = xw0*b0.w + xw1*b1.w + xw2*b2.w + b3.w;
        }
        for (int k = 0; k < 32; k++) {
            float hk = hl[k];
            float t0 = hk * xw0, t1 = hk * xw1, t2 = hk * xw2;
            const float* wr = Wh3s + k * WSTRIDE;
#pragma unroll
            for (int m = 0; m < 8; m++) {
                float4 w0 = ((const float4*)(wr +  0))[m];
                float4 w1 = ((const float4*)(wr + 32))[m];
                float4 w2 = ((const float4*)(wr + 64))[m];
                float4 w3 = ((const float4*)(wr + 96))[m];
                o1[4*m+0] += t0*w0.x + t1*w1.x + t2*w2.x + hk*w3.x;
                o1[4*m+1] += t0*w0.y + t1*w1.y + t2*w2.y + hk*w3.y;
                o1[4*m+2] += t0*w0.z + t1*w1.z + t2*w2.z + hk*w3.z;
                o1[4*m+3] += t0*w0.w + t1*w1.w + t2*w2.w + hk*w3.w;
            }
        }

        // activations to shared (a[32]=1 folds the b2 term)
#pragma unroll
        for (int j = 0; j < 32; j++) als[j * BLOCK + tid] = leakyf(o1[j]);
        als[32 * BLOCK + tid] = 1.0f;

        // layer 2
        float o2[32];
#pragma unroll
        for (int j = 0; j < 32; j++) o2[j] = 0.0f;
        for (int i = 0; i < 33; i++) {
            float ai = als[i * BLOCK + tid];
            const float4* br = (const float4*)(bh3s + 128 + i * 32);
#pragma unroll
            for (int m = 0; m < 8; m++) {
                float4 w = br[m];
                o2[4*m+0] += ai * w.x; o2[4*m+1] += ai * w.y;
                o2[4*m+2] += ai * w.z; o2[4*m+3] += ai * w.w;
            }
        }
        for (int k = 0; k < 32; k++) {
            float hk = hl[k];
            const float* wr = Wh3s + k * WSTRIDE + 128;
            for (int i = 0; i < 33; i++) {
                float t = hk * als[i * BLOCK + tid];
                const float4* w4 = (const float4*)(wr + i * 32);
#pragma unroll
                for (int m = 0; m < 8; m++) {
                    float4 w = w4[m];
                    o2[4*m+0] += t * w.x; o2[4*m+1] += t * w.y;
                    o2[4*m+2] += t * w.z; o2[4*m+3] += t * w.w;
                }
            }
        }

        float a2[32];
#pragma unroll
        for (int j = 0; j < 32; j++) a2[j] = leakyf(o2[j]);

        // layer 3 (cols 1184..1215 = W3, col 1216 = b3)
        float w3a[33];
#pragma unroll
        for (int j = 0; j < 33; j++) w3a[j] = 0.0f;
        for (int k = 0; k < 32; k++) {
            float hk = hl[k];
            const float* wr = Wh3s + k * WSTRIDE + 1184;
#pragma unroll
            for (int m = 0; m < 8; m++) {
                float4 w = ((const float4*)wr)[m];
                w3a[4*m+0] += hk * w.x; w3a[4*m+1] += hk * w.y;
                w3a[4*m+2] += hk * w.z; w3a[4*m+3] += hk * w.w;
            }
            w3a[32] += hk * wr[32];
        }

        float acc = w3a[32] + bh3s[1216];
#pragma unroll
        for (int j = 0; j < 32; j++) acc += a2[j] * (w3a[j] + bh3s[1184 + j]);

        out_scalar[p] = acc;
    }
}

extern "C" void kernel_launch(void* const* d_in, const int* in_sizes, int n_in,
                              void* d_out, int out_size)
{
    (void)in_sizes; (void)n_in; (void)out_size;
    // inputs: 0 pcl (unused), 1 pcl_mem, 2 c_plane, 3 Wh1, 4 bh1, 5 Wh2, 6 bh2, 7 Wh3, 8 bh3
    const float* pcl_mem = (const float*)d_in[1];
    const float* c_plane = (const float*)d_in[2];
    const float* Wh1 = (const float*)d_in[3];
    const float* bh1 = (const float*)d_in[4];
    const float* Wh2 = (const float*)d_in[5];
    const float* bh2 = (const float*)d_in[6];
    const float* Wh3 = (const float*)d_in[7];
    const float* bh3 = (const float*)d_in[8];

    float* out   = (float*)d_out;            // [B*N] scalar out first
    float* feats = out + (size_t)BB * NN;    // then [B*N*128] feats

    dim3 tg(ZYX / 32, CCH / 32, BB);
    transpose_kernel<<<tg, dim3(32, 8, 1)>>>(c_plane);

    size_t smem = (size_t)(32 * WSTRIDE + 4096 + 1024 + WSTRIDE + 32 + 32 + 33 * BLOCK) * sizeof(float);
    cudaFuncSetAttribute(fused_decoder_kernel,
                         cudaFuncAttributeMaxDynamicSharedMemorySize, (int)smem);
    fused_decoder_kernel<<<512, BLOCK, smem>>>(pcl_mem, Wh1, bh1, Wh2, bh2,
                                               Wh3, bh3, out, feats);
}

// round 5
// speedup vs baseline: 1.1263x; 1.1263x over previous
#include <cuda_runtime.h>

#define BB 2
#define NN 65536
#define CCH 128
#define ZYX (64*64*64)
#define TP 1217
#define WSTRIDE 1220
#define BLOCK 256
#define NPTS (BB * NN)

typedef unsigned long long u64;

__device__ float g_ct[(size_t)BB * ZYX * CCH]; // c_plane transposed to [B, ZYX, C]

__device__ __forceinline__ float leakyf(float v) { return v >= 0.0f ? v : 0.01f * v; }

__device__ __forceinline__ float src_idx(float v) {
    float g = fminf(fmaxf((2.0f * v) / 63.0f - 1.0f, -2.0f), 2.0f);
    return fminf(fmaxf((g + 1.0f) * 0.5f * 63.0f, 0.0f), 63.0f);
}

// ---- packed f32x2 helpers (sm_100+; PTX-only, ptxas won't auto-fuse) ----
__device__ __forceinline__ u64 pk2(float v) {
    u64 r; asm("mov.b64 %0, {%1, %1};" : "=l"(r) : "f"(v)); return r;
}
__device__ __forceinline__ void fma2(u64 &d, u64 a, u64 b) {
    asm("fma.rn.f32x2 %0, %1, %2, %0;" : "+l"(d) : "l"(a), "l"(b));
}
__device__ __forceinline__ u64 mul2(u64 a, u64 b) {
    u64 r; asm("mul.rn.f32x2 %0, %1, %2;" : "=l"(r) : "l"(a), "l"(b)); return r;
}
__device__ __forceinline__ u64 add2(u64 a, u64 b) {
    u64 r; asm("add.rn.f32x2 %0, %1, %2;" : "=l"(r) : "l"(a), "l"(b)); return r;
}
__device__ __forceinline__ float2 upk2(u64 v) {
    float2 r; asm("mov.b64 {%0, %1}, %2;" : "=f"(r.x), "=f"(r.y) : "l"(v)); return r;
}
// packed lerp: r = a*om + b*w  (per 2-float half)
__device__ __forceinline__ ulonglong2 lerpp(ulonglong2 a, ulonglong2 b, u64 w2, u64 om2) {
    ulonglong2 r;
    r.x = mul2(a.x, om2); fma2(r.x, b.x, w2);
    r.y = mul2(a.y, om2); fma2(r.y, b.y, w2);
    return r;
}

// [B, C, ZYX] -> [B, ZYX, C]
__global__ void transpose_kernel(const float* __restrict__ in) {
    __shared__ float tile[32][33];
    int b = blockIdx.z, s0 = blockIdx.x * 32, c0 = blockIdx.y * 32;
    const float* ib = in   + (size_t)b * CCH * ZYX;
    float*       ob = g_ct + (size_t)b * ZYX * CCH;
    int tx = threadIdx.x, ty = threadIdx.y;
#pragma unroll
    for (int j = 0; j < 32; j += 8)
        tile[ty + j][tx] = ib[(size_t)(c0 + ty + j) * ZYX + s0 + tx];
    __syncthreads();
#pragma unroll
    for (int j = 0; j < 32; j += 8)
        ob[(size_t)(s0 + ty + j) * CCH + c0 + tx] = tile[tx][ty + j];
}

__global__ __launch_bounds__(BLOCK, 1)
void fused_decoder_kernel(const float* __restrict__ pm,
                          const float* __restrict__ Wh1,
                          const float* __restrict__ bh1,
                          const float* __restrict__ Wh2,
                          const float* __restrict__ bh2,
                          const float* __restrict__ Wh3,
                          const float* __restrict__ bh3,
                          float* __restrict__ out_scalar,
                          float* __restrict__ out_feats)
{
    extern __shared__ float sm[];
    float* Wh3s = sm;                    // 32*WSTRIDE
    float* Wh1s = Wh3s + 32 * WSTRIDE;   // 4096
    float* Wh2s = Wh1s + 4096;           // 1024
    float* bh3s = Wh2s + 1024;           // WSTRIDE
    float* bh1s = bh3s + WSTRIDE;        // 32
    float* bh2s = bh1s + 32;             // 32
    float* als  = bh2s + 32;             // 33*BLOCK

    const int tid = threadIdx.x;

    for (int i = tid; i < 32 * TP; i += BLOCK) {
        int k = i / TP, c = i - k * TP;
        Wh3s[k * WSTRIDE + c] = Wh3[i];
    }
    for (int i = tid; i < 4096; i += BLOCK) Wh1s[i] = Wh1[i];
    for (int i = tid; i < 1024; i += BLOCK) Wh2s[i] = Wh2[i];
    for (int i = tid; i < TP;   i += BLOCK) bh3s[i] = bh3[i];
    if (tid < 32) { bh1s[tid] = bh1[tid]; bh2s[tid] = bh2[tid]; }
    __syncthreads();

    const int stride = gridDim.x * BLOCK;
    for (int p = blockIdx.x * BLOCK + tid; p < NPTS; p += stride) {
        const float vx = pm[3 * p + 0];
        const float vy = pm[3 * p + 1];
        const float vz = pm[3 * p + 2];

        float ix = src_idx(vx), iy = src_idx(vy), iz = src_idx(vz);
        float fx = floorf(ix), fy = floorf(iy), fz = floorf(iz);
        float wx = ix - fx, wy = iy - fy, wz = iz - fz;
        int x0 = min(max((int)fx, 0), 63); int x1 = min(x0 + 1, 63);
        int y0 = min(max((int)fy, 0), 63); int y1 = min(y0 + 1, 63);
        int z0 = min(max((int)fz, 0), 63); int z1 = min(z0 + 1, 63);

        const int b = p >> 16;
        const float* cb = g_ct + (size_t)b * ZYX * CCH;
        const ulonglong2* q000 = (const ulonglong2*)(cb + (size_t)((z0 * 64 + y0) * 64 + x0) * CCH);
        const ulonglong2* q001 = (const ulonglong2*)(cb + (size_t)((z0 * 64 + y0) * 64 + x1) * CCH);
        const ulonglong2* q010 = (const ulonglong2*)(cb + (size_t)((z0 * 64 + y1) * 64 + x0) * CCH);
        const ulonglong2* q011 = (const ulonglong2*)(cb + (size_t)((z0 * 64 + y1) * 64 + x1) * CCH);
        const ulonglong2* q100 = (const ulonglong2*)(cb + (size_t)((z1 * 64 + y0) * 64 + x0) * CCH);
        const ulonglong2* q101 = (const ulonglong2*)(cb + (size_t)((z1 * 64 + y0) * 64 + x1) * CCH);
        const ulonglong2* q110 = (const ulonglong2*)(cb + (size_t)((z1 * 64 + y1) * 64 + x0) * CCH);
        const ulonglong2* q111 = (const ulonglong2*)(cb + (size_t)((z1 * 64 + y1) * 64 + x1) * CCH);

        const u64 wx2 = pk2(wx), omx2 = pk2(1.0f - wx);
        const u64 wy2 = pk2(wy), omy2 = pk2(1.0f - wy);
        const u64 wz2 = pk2(wz), omz2 = pk2(1.0f - wz);

        u64 h1p[16];
#pragma unroll
        for (int m = 0; m < 16; m++) h1p[m] = 0ULL;

        ulonglong2* fo = (ulonglong2*)(out_feats + (size_t)p * CCH);

        // gather + trilinear + feats store + feats@Wh1 (all packed)
#pragma unroll 2
        for (int cc = 0; cc < 32; ++cc) {
            ulonglong2 a000 = q000[cc], a001 = q001[cc];
            ulonglong2 a010 = q010[cc], a011 = q011[cc];
            ulonglong2 a100 = q100[cc], a101 = q101[cc];
            ulonglong2 a110 = q110[cc], a111 = q111[cc];

            ulonglong2 c00 = lerpp(a000, a001, wx2, omx2);
            ulonglong2 c01 = lerpp(a010, a011, wx2, omx2);
            ulonglong2 c10 = lerpp(a100, a101, wx2, omx2);
            ulonglong2 c11 = lerpp(a110, a111, wx2, omx2);
            ulonglong2 c0  = lerpp(c00, c01, wy2, omy2);
            ulonglong2 c1  = lerpp(c10, c11, wy2, omy2);
            ulonglong2 f   = lerpp(c0, c1, wz2, omz2);

            fo[cc] = f;

            float2 f01 = upk2(f.x), f23 = upk2(f.y);
            float fa[4] = { f01.x, f01.y, f23.x, f23.y };
#pragma unroll
            for (int e = 0; e < 4; e++) {
                u64 fc2 = pk2(fa[e]);
                const ulonglong2* wr = (const ulonglong2*)(Wh1s + (cc * 4 + e) * 32);
#pragma unroll
                for (int m = 0; m < 8; m++) {
                    ulonglong2 w = wr[m];
                    fma2(h1p[2 * m],     w.x, fc2);
                    fma2(h1p[2 * m + 1], w.y, fc2);
                }
            }
        }

        float h1[32];
#pragma unroll
        for (int m = 0; m < 16; m++) {
            float2 v = upk2(h1p[m]);
            h1[2 * m]     = leakyf(v.x + bh1s[2 * m]);
            h1[2 * m + 1] = leakyf(v.y + bh1s[2 * m + 1]);
        }

        // h @ Wh2
        u64 h2p[16];
#pragma unroll
        for (int m = 0; m < 16; m++) h2p[m] = 0ULL;
#pragma unroll 4
        for (int k = 0; k < 32; k++) {
            u64 hk2 = pk2(h1[k]);
            const ulonglong2* wr = (const ulonglong2*)(Wh2s + k * 32);
#pragma unroll
            for (int m = 0; m < 8; m++) {
                ulonglong2 w = wr[m];
                fma2(h2p[2 * m],     w.x, hk2);
                fma2(h2p[2 * m + 1], w.y, hk2);
            }
        }

        float hl[32];
#pragma unroll
        for (int m = 0; m < 16; m++) {
            float2 v = upk2(h2p[m]);
            hl[2 * m]     = leakyf(v.x + bh2s[2 * m]);
            hl[2 * m + 1] = leakyf(v.y + bh2s[2 * m + 1]);
        }

        // ---- generated MLP layer 1
        const float xw0 = vx - truncf(vx) - 0.5f;
        const float xw1 = vy - truncf(vy) - 0.5f;
        const float xw2 = vz - truncf(vz) - 0.5f;
        const u64 xw0_2 = pk2(xw0), xw1_2 = pk2(xw1), xw2_2 = pk2(xw2);

        u64 o1p[16];
#pragma unroll
        for (int m = 0; m < 8; m++) {
            ulonglong2 b0 = ((const ulonglong2*)(bh3s +  0))[m];
            ulonglong2 b1 = ((const ulonglong2*)(bh3s + 32))[m];
            ulonglong2 b2 = ((const ulonglong2*)(bh3s + 64))[m];
            ulonglong2 b3 = ((const ulonglong2*)(bh3s + 96))[m];
            u64 r0 = mul2(b0.x, xw0_2); fma2(r0, b1.x, xw1_2); fma2(r0, b2.x, xw2_2);
            u64 r1 = mul2(b0.y, xw0_2); fma2(r1, b1.y, xw1_2); fma2(r1, b2.y, xw2_2);
            o1p[2 * m]     = add2(r0, b3.x);
            o1p[2 * m + 1] = add2(r1, b3.y);
        }
#pragma unroll 2
        for (int k = 0; k < 32; k++) {
            float hk = hl[k];
            u64 t0 = pk2(hk * xw0), t1 = pk2(hk * xw1), t2 = pk2(hk * xw2), hk2 = pk2(hk);
            const float* wr = Wh3s + k * WSTRIDE;
#pragma unroll
            for (int m = 0; m < 8; m++) {
                ulonglong2 w0 = ((const ulonglong2*)(wr +  0))[m];
                ulonglong2 w1 = ((const ulonglong2*)(wr + 32))[m];
                ulonglong2 w2 = ((const ulonglong2*)(wr + 64))[m];
                ulonglong2 w3 = ((const ulonglong2*)(wr + 96))[m];
                u64 a0 = o1p[2 * m], a1 = o1p[2 * m + 1];
                fma2(a0, w0.x, t0); fma2(a1, w0.y, t0);
                fma2(a0, w1.x, t1); fma2(a1, w1.y, t1);
                fma2(a0, w2.x, t2); fma2(a1, w2.y, t2);
                fma2(a0, w3.x, hk2); fma2(a1, w3.y, hk2);
                o1p[2 * m] = a0; o1p[2 * m + 1] = a1;
            }
        }

        // activations to shared (a[32] = 1 folds the b2 term)
#pragma unroll
        for (int m = 0; m < 16; m++) {
            float2 v = upk2(o1p[m]);
            als[(2 * m) * BLOCK + tid]     = leakyf(v.x);
            als[(2 * m + 1) * BLOCK + tid] = leakyf(v.y);
        }
        als[32 * BLOCK + tid] = 1.0f;

        // ---- layer 2: bias part
        u64 o2p[16];
#pragma unroll
        for (int m = 0; m < 16; m++) o2p[m] = 0ULL;
        for (int i = 0; i < 33; i++) {
            u64 ai2 = pk2(als[i * BLOCK + tid]);
            const ulonglong2* br = (const ulonglong2*)(bh3s + 128 + i * 32);
#pragma unroll
            for (int m = 0; m < 8; m++) {
                ulonglong2 w = br[m];
                fma2(o2p[2 * m],     w.x, ai2);
                fma2(o2p[2 * m + 1], w.y, ai2);
            }
        }
        // ---- layer 2: main contraction (dominant loop)
        for (int i = 0; i < 33; i++) {
            const float ai = als[i * BLOCK + tid];
            const float* base = Wh3s + 128 + i * 32;
#pragma unroll 8
            for (int k = 0; k < 32; k++) {
                u64 t2p = pk2(hl[k] * ai);
                const ulonglong2* w4 = (const ulonglong2*)(base + k * WSTRIDE);
#pragma unroll
                for (int m = 0; m < 8; m++) {
                    ulonglong2 w = w4[m];
                    fma2(o2p[2 * m],     w.x, t2p);
                    fma2(o2p[2 * m + 1], w.y, t2p);
                }
            }
        }

        float a2[32];
#pragma unroll
        for (int m = 0; m < 16; m++) {
            float2 v = upk2(o2p[m]);
            a2[2 * m]     = leakyf(v.x);
            a2[2 * m + 1] = leakyf(v.y);
        }

        // ---- layer 3 (cols 1184..1215 = W3, col 1216 = b3)
        u64 w3p[16];
#pragma unroll
        for (int m = 0; m < 16; m++) w3p[m] = 0ULL;
        float w3b = 0.0f;
#pragma unroll 4
        for (int k = 0; k < 32; k++) {
            float hk = hl[k];
            u64 hk2 = pk2(hk);
            const float* wr = Wh3s + k * WSTRIDE + 1184;
#pragma unroll
            for (int m = 0; m < 8; m++) {
                ulonglong2 w = ((const ulonglong2*)wr)[m];
                fma2(w3p[2 * m],     w.x, hk2);
                fma2(w3p[2 * m + 1], w.y, hk2);
            }
            w3b += hk * wr[32];
        }

        float acc = w3b + bh3s[1216];
#pragma unroll
        for (int m = 0; m < 16; m++) {
            float2 v = upk2(w3p[m]);
            acc += a2[2 * m]     * (v.x + bh3s[1184 + 2 * m]);
            acc += a2[2 * m + 1] * (v.y + bh3s[1184 + 2 * m + 1]);
        }

        out_scalar[p] = acc;
    }
}

extern "C" void kernel_launch(void* const* d_in, const int* in_sizes, int n_in,
                              void* d_out, int out_size)
{
    (void)in_sizes; (void)n_in; (void)out_size;
    // inputs: 0 pcl (unused), 1 pcl_mem, 2 c_plane, 3 Wh1, 4 bh1, 5 Wh2, 6 bh2, 7 Wh3, 8 bh3
    const float* pcl_mem = (const float*)d_in[1];
    const float* c_plane = (const float*)d_in[2];
    const float* Wh1 = (const float*)d_in[3];
    const float* bh1 = (const float*)d_in[4];
    const float* Wh2 = (const float*)d_in[5];
    const float* bh2 = (const float*)d_in[6];
    const float* Wh3 = (const float*)d_in[7];
    const float* bh3 = (const float*)d_in[8];

    float* out   = (float*)d_out;            // [B*N] scalar out first
    float* feats = out + (size_t)BB * NN;    // then [B*N*128] feats

    dim3 tg(ZYX / 32, CCH / 32, BB);
    transpose_kernel<<<tg, dim3(32, 8, 1)>>>(c_plane);

    size_t smem = (size_t)(32 * WSTRIDE + 4096 + 1024 + WSTRIDE + 32 + 32 + 33 * BLOCK) * sizeof(float);
    cudaFuncSetAttribute(fused_decoder_kernel,
                         cudaFuncAttributeMaxDynamicSharedMemorySize, (int)smem);
    // persistent: 1 CTA per SM (148), weights loaded once per SM
    fused_decoder_kernel<<<148, BLOCK, smem>>>(pcl_mem, Wh1, bh1, Wh2, bh2,
                                               Wh3, bh3, out, feats);
}

// round 6
// speedup vs baseline: 1.1795x; 1.0472x over previous
#include <cuda_runtime.h>

#define BB 2
#define NN 65536
#define CCH 128
#define ZYX (64*64*64)
#define TP 1217
#define WSTRIDE 1220
#define BLOCK 256
#define NPTS (BB * NN)

typedef unsigned long long u64;

__device__ float g_ct[(size_t)BB * ZYX * CCH]; // c_plane transposed to [B, ZYX, C]

__device__ __forceinline__ float leakyf(float v) { return v >= 0.0f ? v : 0.01f * v; }

__device__ __forceinline__ float src_idx(float v) {
    float g = fminf(fmaxf((2.0f * v) / 63.0f - 1.0f, -2.0f), 2.0f);
    return fminf(fmaxf((g + 1.0f) * 0.5f * 63.0f, 0.0f), 63.0f);
}

// ---- packed f32x2 helpers (sm_100+) ----
__device__ __forceinline__ u64 pk2(float v) {
    u64 r; asm("mov.b64 %0, {%1, %1};" : "=l"(r) : "f"(v)); return r;
}
__device__ __forceinline__ void fma2(u64 &d, u64 a, u64 b) {
    asm("fma.rn.f32x2 %0, %1, %2, %0;" : "+l"(d) : "l"(a), "l"(b));
}
__device__ __forceinline__ u64 mul2(u64 a, u64 b) {
    u64 r; asm("mul.rn.f32x2 %0, %1, %2;" : "=l"(r) : "l"(a), "l"(b)); return r;
}
__device__ __forceinline__ u64 add2(u64 a, u64 b) {
    u64 r; asm("add.rn.f32x2 %0, %1, %2;" : "=l"(r) : "l"(a), "l"(b)); return r;
}
__device__ __forceinline__ float2 upk2(u64 v) {
    float2 r; asm("mov.b64 {%0, %1}, %2;" : "=f"(r.x), "=f"(r.y) : "l"(v)); return r;
}
__device__ __forceinline__ ulonglong2 lerpp(ulonglong2 a, ulonglong2 b, u64 w2, u64 om2) {
    ulonglong2 r;
    r.x = mul2(a.x, om2); fma2(r.x, b.x, w2);
    r.y = mul2(a.y, om2); fma2(r.y, b.y, w2);
    return r;
}

// [B, C, ZYX] -> [B, ZYX, C]
__global__ void transpose_kernel(const float* __restrict__ in) {
    __shared__ float tile[32][33];
    int b = blockIdx.z, s0 = blockIdx.x * 32, c0 = blockIdx.y * 32;
    const float* ib = in   + (size_t)b * CCH * ZYX;
    float*       ob = g_ct + (size_t)b * ZYX * CCH;
    int tx = threadIdx.x, ty = threadIdx.y;
#pragma unroll
    for (int j = 0; j < 32; j += 8)
        tile[ty + j][tx] = ib[(size_t)(c0 + ty + j) * ZYX + s0 + tx];
    __syncthreads();
#pragma unroll
    for (int j = 0; j < 32; j += 8)
        ob[(size_t)(s0 + ty + j) * CCH + c0 + tx] = tile[tx][ty + j];
}

// Phase 1 for one point: trilinear gather (+feats store), feats@Wh1, h@Wh2.
// Produces hl[32] (leaky hidden state) and xw[3]. All static indexing inside.
__device__ __forceinline__ void phase1(const float* __restrict__ pm, int p,
                                       const float* Wh1s, const float* bh1s,
                                       const float* Wh2s, const float* bh2s,
                                       float* __restrict__ out_feats,
                                       float hl[32], float xw[3])
{
    const float vx = pm[3 * p + 0];
    const float vy = pm[3 * p + 1];
    const float vz = pm[3 * p + 2];

    float ix = src_idx(vx), iy = src_idx(vy), iz = src_idx(vz);
    float fx = floorf(ix), fy = floorf(iy), fz = floorf(iz);
    float wx = ix - fx, wy = iy - fy, wz = iz - fz;
    int x0 = min(max((int)fx, 0), 63); int x1 = min(x0 + 1, 63);
    int y0 = min(max((int)fy, 0), 63); int y1 = min(y0 + 1, 63);
    int z0 = min(max((int)fz, 0), 63); int z1 = min(z0 + 1, 63);

    const int b = p >> 16;
    const float* cb = g_ct + (size_t)b * ZYX * CCH;
    const ulonglong2* q000 = (const ulonglong2*)(cb + (size_t)((z0 * 64 + y0) * 64 + x0) * CCH);
    const ulonglong2* q001 = (const ulonglong2*)(cb + (size_t)((z0 * 64 + y0) * 64 + x1) * CCH);
    const ulonglong2* q010 = (const ulonglong2*)(cb + (size_t)((z0 * 64 + y1) * 64 + x0) * CCH);
    const ulonglong2* q011 = (const ulonglong2*)(cb + (size_t)((z0 * 64 + y1) * 64 + x1) * CCH);
    const ulonglong2* q100 = (const ulonglong2*)(cb + (size_t)((z1 * 64 + y0) * 64 + x0) * CCH);
    const ulonglong2* q101 = (const ulonglong2*)(cb + (size_t)((z1 * 64 + y0) * 64 + x1) * CCH);
    const ulonglong2* q110 = (const ulonglong2*)(cb + (size_t)((z1 * 64 + y1) * 64 + x0) * CCH);
    const ulonglong2* q111 = (const ulonglong2*)(cb + (size_t)((z1 * 64 + y1) * 64 + x1) * CCH);

    const u64 wx2 = pk2(wx), omx2 = pk2(1.0f - wx);
    const u64 wy2 = pk2(wy), omy2 = pk2(1.0f - wy);
    const u64 wz2 = pk2(wz), omz2 = pk2(1.0f - wz);

    u64 h1p[16];
#pragma unroll
    for (int m = 0; m < 16; m++) h1p[m] = 0ULL;

    ulonglong2* fo = (ulonglong2*)(out_feats + (size_t)p * CCH);

#pragma unroll 2
    for (int cc = 0; cc < 32; ++cc) {
        ulonglong2 a000 = q000[cc], a001 = q001[cc];
        ulonglong2 a010 = q010[cc], a011 = q011[cc];
        ulonglong2 a100 = q100[cc], a101 = q101[cc];
        ulonglong2 a110 = q110[cc], a111 = q111[cc];

        ulonglong2 c00 = lerpp(a000, a001, wx2, omx2);
        ulonglong2 c01 = lerpp(a010, a011, wx2, omx2);
        ulonglong2 c10 = lerpp(a100, a101, wx2, omx2);
        ulonglong2 c11 = lerpp(a110, a111, wx2, omx2);
        ulonglong2 c0  = lerpp(c00, c01, wy2, omy2);
        ulonglong2 c1  = lerpp(c10, c11, wy2, omy2);
        ulonglong2 f   = lerpp(c0, c1, wz2, omz2);

        fo[cc] = f;

        float2 f01 = upk2(f.x), f23 = upk2(f.y);
        float fa[4] = { f01.x, f01.y, f23.x, f23.y };
#pragma unroll
        for (int e = 0; e < 4; e++) {
            u64 fc2 = pk2(fa[e]);
            const ulonglong2* wr = (const ulonglong2*)(Wh1s + (cc * 4 + e) * 32);
#pragma unroll
            for (int m = 0; m < 8; m++) {
                ulonglong2 w = wr[m];
                fma2(h1p[2 * m],     w.x, fc2);
                fma2(h1p[2 * m + 1], w.y, fc2);
            }
        }
    }

    float h1[32];
#pragma unroll
    for (int m = 0; m < 16; m++) {
        float2 v = upk2(h1p[m]);
        h1[2 * m]     = leakyf(v.x + bh1s[2 * m]);
        h1[2 * m + 1] = leakyf(v.y + bh1s[2 * m + 1]);
    }

    u64 h2p[16];
#pragma unroll
    for (int m = 0; m < 16; m++) h2p[m] = 0ULL;
#pragma unroll
    for (int k = 0; k < 32; k++) {
        u64 hk2 = pk2(h1[k]);
        const ulonglong2* wr = (const ulonglong2*)(Wh2s + k * 32);
#pragma unroll
        for (int m = 0; m < 8; m++) {
            ulonglong2 w = wr[m];
            fma2(h2p[2 * m],     w.x, hk2);
            fma2(h2p[2 * m + 1], w.y, hk2);
        }
    }

#pragma unroll
    for (int m = 0; m < 16; m++) {
        float2 v = upk2(h2p[m]);
        hl[2 * m]     = leakyf(v.x + bh2s[2 * m]);
        hl[2 * m + 1] = leakyf(v.y + bh2s[2 * m + 1]);
    }

    xw[0] = vx - truncf(vx) - 0.5f;
    xw[1] = vy - truncf(vy) - 0.5f;
    xw[2] = vz - truncf(vz) - 0.5f;
}

__global__ __launch_bounds__(BLOCK, 1)
void fused_decoder_kernel(const float* __restrict__ pm,
                          const float* __restrict__ Wh1,
                          const float* __restrict__ bh1,
                          const float* __restrict__ Wh2,
                          const float* __restrict__ bh2,
                          const float* __restrict__ Wh3,
                          const float* __restrict__ bh3,
                          float* __restrict__ out_scalar,
                          float* __restrict__ out_feats)
{
    extern __shared__ float sm[];
    float* Wh3s = sm;                    // 32*WSTRIDE
    float* Wh1s = Wh3s + 32 * WSTRIDE;   // 4096
    float* Wh2s = Wh1s + 4096;           // 1024
    float* bh3s = Wh2s + 1024;           // WSTRIDE
    float* bh1s = bh3s + WSTRIDE;        // 32
    float* bh2s = bh1s + 32;             // 32

    const int tid = threadIdx.x;

    for (int i = tid; i < 32 * TP; i += BLOCK) {
        int k = i / TP, c = i - k * TP;
        Wh3s[k * WSTRIDE + c] = Wh3[i];
    }
    for (int i = tid; i < 4096; i += BLOCK) Wh1s[i] = Wh1[i];
    for (int i = tid; i < 1024; i += BLOCK) Wh2s[i] = Wh2[i];
    for (int i = tid; i < TP;   i += BLOCK) bh3s[i] = bh3[i];
    if (tid < 32) { bh1s[tid] = bh1[tid]; bh2s[tid] = bh2[tid]; }
    __syncthreads();

    const int t0 = blockIdx.x * BLOCK + tid;  // grid 128 * 256 = 32768 threads

#pragma unroll 1
    for (int rep = 0; rep < 2; rep++) {
        const int pA = t0 + rep * 32768;   // batch 0 point
        const int pB = pA + 65536;         // batch 1 point

        float hlA[32], xwA[3];
        float hlB[32], xwB[3];
        phase1(pm, pA, Wh1s, bh1s, Wh2s, bh2s, out_feats, hlA, xwA);
        phase1(pm, pB, Wh1s, bh1s, Wh2s, bh2s, out_feats, hlB, xwB);

        // ---- generated MLP layer 1 (joint over the pair)
        u64 o1A[16], o1B[16];
        {
            const u64 x0A = pk2(xwA[0]), x1A = pk2(xwA[1]), x2A = pk2(xwA[2]);
            const u64 x0B = pk2(xwB[0]), x1B = pk2(xwB[1]), x2B = pk2(xwB[2]);
#pragma unroll
            for (int m = 0; m < 8; m++) {
                ulonglong2 b0 = ((const ulonglong2*)(bh3s +  0))[m];
                ulonglong2 b1 = ((const ulonglong2*)(bh3s + 32))[m];
                ulonglong2 b2 = ((const ulonglong2*)(bh3s + 64))[m];
                ulonglong2 b3 = ((const ulonglong2*)(bh3s + 96))[m];
                u64 rA0 = mul2(b0.x, x0A); fma2(rA0, b1.x, x1A); fma2(rA0, b2.x, x2A);
                u64 rA1 = mul2(b0.y, x0A); fma2(rA1, b1.y, x1A); fma2(rA1, b2.y, x2A);
                o1A[2*m]   = add2(rA0, b3.x);
                o1A[2*m+1] = add2(rA1, b3.y);
                u64 rB0 = mul2(b0.x, x0B); fma2(rB0, b1.x, x1B); fma2(rB0, b2.x, x2B);
                u64 rB1 = mul2(b0.y, x0B); fma2(rB1, b1.y, x1B); fma2(rB1, b2.y, x2B);
                o1B[2*m]   = add2(rB0, b3.x);
                o1B[2*m+1] = add2(rB1, b3.y);
            }
#pragma unroll 1
            for (int k = 0; k < 32; k++) {
                float hA = hlA[k], hB = hlB[k];
                u64 t0A = pk2(hA * xwA[0]), t1A = pk2(hA * xwA[1]), t2A = pk2(hA * xwA[2]), hA2 = pk2(hA);
                u64 t0B = pk2(hB * xwB[0]), t1B = pk2(hB * xwB[1]), t2B = pk2(hB * xwB[2]), hB2 = pk2(hB);
                const float* wr = Wh3s + k * WSTRIDE;
#pragma unroll
                for (int m = 0; m < 8; m++) {
                    ulonglong2 w0 = ((const ulonglong2*)(wr +  0))[m];
                    ulonglong2 w1 = ((const ulonglong2*)(wr + 32))[m];
                    ulonglong2 w2 = ((const ulonglong2*)(wr + 64))[m];
                    ulonglong2 w3 = ((const ulonglong2*)(wr + 96))[m];
                    u64 aA0 = o1A[2*m], aA1 = o1A[2*m+1];
                    fma2(aA0, w0.x, t0A); fma2(aA1, w0.y, t0A);
                    fma2(aA0, w1.x, t1A); fma2(aA1, w1.y, t1A);
                    fma2(aA0, w2.x, t2A); fma2(aA1, w2.y, t2A);
                    fma2(aA0, w3.x, hA2); fma2(aA1, w3.y, hA2);
                    o1A[2*m] = aA0; o1A[2*m+1] = aA1;
                    u64 aB0 = o1B[2*m], aB1 = o1B[2*m+1];
                    fma2(aB0, w0.x, t0B); fma2(aB1, w0.y, t0B);
                    fma2(aB0, w1.x, t1B); fma2(aB1, w1.y, t1B);
                    fma2(aB0, w2.x, t2B); fma2(aB1, w2.y, t2B);
                    fma2(aB0, w3.x, hB2); fma2(aB1, w3.y, hB2);
                    o1B[2*m] = aB0; o1B[2*m+1] = aB1;
                }
            }
        }

        // activations in REGISTERS (statically indexed everywhere below)
        float aA[33], aB[33];
#pragma unroll
        for (int m = 0; m < 16; m++) {
            float2 vA = upk2(o1A[m]);
            aA[2*m] = leakyf(vA.x); aA[2*m+1] = leakyf(vA.y);
            float2 vB = upk2(o1B[m]);
            aB[2*m] = leakyf(vB.x); aB[2*m+1] = leakyf(vB.y);
        }
        aA[32] = 1.0f; aB[32] = 1.0f;

        // ---- layer 2: bias part (i unrolled; weights shared across pair)
        u64 o2A[16], o2B[16];
#pragma unroll
        for (int m = 0; m < 16; m++) { o2A[m] = 0ULL; o2B[m] = 0ULL; }
#pragma unroll
        for (int i = 0; i < 33; i++) {
            u64 aiA = pk2(aA[i]);
            u64 aiB = pk2(aB[i]);
            const ulonglong2* br = (const ulonglong2*)(bh3s + 128 + i * 32);
#pragma unroll
            for (int m = 0; m < 8; m++) {
                ulonglong2 w = br[m];
                fma2(o2A[2*m], w.x, aiA); fma2(o2A[2*m+1], w.y, aiA);
                fma2(o2B[2*m], w.x, aiB); fma2(o2B[2*m+1], w.y, aiB);
            }
        }
        // ---- layer 2: main contraction (dominant loop; 8 LDS -> 32 fma2)
#pragma unroll 1
        for (int k = 0; k < 32; k++) {
            const float hA = hlA[k], hB = hlB[k];
            const float* wr = Wh3s + k * WSTRIDE + 128;
#pragma unroll
            for (int i = 0; i < 33; i++) {
                u64 tA = pk2(hA * aA[i]);
                u64 tB = pk2(hB * aB[i]);
                const ulonglong2* w4 = (const ulonglong2*)(wr + i * 32);
#pragma unroll
                for (int m = 0; m < 8; m++) {
                    ulonglong2 w = w4[m];
                    fma2(o2A[2*m], w.x, tA); fma2(o2A[2*m+1], w.y, tA);
                    fma2(o2B[2*m], w.x, tB); fma2(o2B[2*m+1], w.y, tB);
                }
            }
        }

        float a2A[32], a2B[32];
#pragma unroll
        for (int m = 0; m < 16; m++) {
            float2 vA = upk2(o2A[m]);
            a2A[2*m] = leakyf(vA.x); a2A[2*m+1] = leakyf(vA.y);
            float2 vB = upk2(o2B[m]);
            a2B[2*m] = leakyf(vB.x); a2B[2*m+1] = leakyf(vB.y);
        }

        // ---- layer 3 (cols 1184..1215 = W3, col 1216 = b3), joint
        u64 w3A[16], w3B[16];
#pragma unroll
        for (int m = 0; m < 16; m++) { w3A[m] = 0ULL; w3B[m] = 0ULL; }
        float w3bA = 0.0f, w3bB = 0.0f;
#pragma unroll 1
        for (int k = 0; k < 32; k++) {
            float hA = hlA[k], hB = hlB[k];
            u64 hA2 = pk2(hA), hB2 = pk2(hB);
            const float* wr = Wh3s + k * WSTRIDE + 1184;
#pragma unroll
            for (int m = 0; m < 8; m++) {
                ulonglong2 w = ((const ulonglong2*)wr)[m];
                fma2(w3A[2*m], w.x, hA2); fma2(w3A[2*m+1], w.y, hA2);
                fma2(w3B[2*m], w.x, hB2); fma2(w3B[2*m+1], w.y, hB2);
            }
            w3bA += hA * wr[32];
            w3bB += hB * wr[32];
        }

        float accA = w3bA + bh3s[1216];
        float accB = w3bB + bh3s[1216];
#pragma unroll
        for (int m = 0; m < 16; m++) {
            float2 vA = upk2(w3A[m]);
            accA += a2A[2*m]   * (vA.x + bh3s[1184 + 2*m]);
            accA += a2A[2*m+1] * (vA.y + bh3s[1184 + 2*m + 1]);
            float2 vB = upk2(w3B[m]);
            accB += a2B[2*m]   * (vB.x + bh3s[1184 + 2*m]);
            accB += a2B[2*m+1] * (vB.y + bh3s[1184 + 2*m + 1]);
        }

        out_scalar[pA] = accA;
        out_scalar[pB] = accB;
    }
}

extern "C" void kernel_launch(void* const* d_in, const int* in_sizes, int n_in,
                              void* d_out, int out_size)
{
    (void)in_sizes; (void)n_in; (void)out_size;
    // inputs: 0 pcl (unused), 1 pcl_mem, 2 c_plane, 3 Wh1, 4 bh1, 5 Wh2, 6 bh2, 7 Wh3, 8 bh3
    const float* pcl_mem = (const float*)d_in[1];
    const float* c_plane = (const float*)d_in[2];
    const float* Wh1 = (const float*)d_in[3];
    const float* bh1 = (const float*)d_in[4];
    const float* Wh2 = (const float*)d_in[5];
    const float* bh2 = (const float*)d_in[6];
    const float* Wh3 = (const float*)d_in[7];
    const float* bh3 = (const float*)d_in[8];

    float* out   = (float*)d_out;            // [B*N] scalar out first
    float* feats = out + (size_t)BB * NN;    // then [B*N*128] feats

    dim3 tg(ZYX / 32, CCH / 32, BB);
    transpose_kernel<<<tg, dim3(32, 8, 1)>>>(c_plane);

    size_t smem = (size_t)(32 * WSTRIDE + 4096 + 1024 + WSTRIDE + 32 + 32) * sizeof(float);
    cudaFuncSetAttribute(fused_decoder_kernel,
                         cudaFuncAttributeMaxDynamicSharedMemorySize, (int)smem);
    // 128 CTAs * 256 threads = 32768 threads; each handles exactly 2 pairs (4 points)
    fused_decoder_kernel<<<128, BLOCK, smem>>>(pcl_mem, Wh1, bh1, Wh2, bh2,
                                               Wh3, bh3, out, feats);
}

// round 7
// speedup vs baseline: 1.1802x; 1.0006x over previous
#include <cuda_runtime.h>

#define BB 2
#define NN 65536
#define CCH 128
#define ZYX (64*64*64)
#define TP 1217
#define WSTRIDE 1220
#define BLOCK 256
#define NPTS (BB * NN)

typedef unsigned long long u64;

__device__ float g_ct[(size_t)BB * ZYX * CCH]; // c_plane transposed to [B, ZYX, C]

__device__ __forceinline__ float leakyf(float v) { return v >= 0.0f ? v : 0.01f * v; }

__device__ __forceinline__ float src_idx(float v) {
    float g = fminf(fmaxf((2.0f * v) / 63.0f - 1.0f, -2.0f), 2.0f);
    return fminf(fmaxf((g + 1.0f) * 0.5f * 63.0f, 0.0f), 63.0f);
}

// ---- packed f32x2 helpers (sm_100+) ----
__device__ __forceinline__ u64 pk2(float v) {
    u64 r; asm("mov.b64 %0, {%1, %1};" : "=l"(r) : "f"(v)); return r;
}
__device__ __forceinline__ void fma2(u64 &d, u64 a, u64 b) {
    asm("fma.rn.f32x2 %0, %1, %2, %0;" : "+l"(d) : "l"(a), "l"(b));
}
__device__ __forceinline__ u64 mul2(u64 a, u64 b) {
    u64 r; asm("mul.rn.f32x2 %0, %1, %2;" : "=l"(r) : "l"(a), "l"(b)); return r;
}
__device__ __forceinline__ u64 add2(u64 a, u64 b) {
    u64 r; asm("add.rn.f32x2 %0, %1, %2;" : "=l"(r) : "l"(a), "l"(b)); return r;
}
__device__ __forceinline__ float2 upk2(u64 v) {
    float2 r; asm("mov.b64 {%0, %1}, %2;" : "=f"(r.x), "=f"(r.y) : "l"(v)); return r;
}
__device__ __forceinline__ ulonglong2 lerpp(ulonglong2 a, ulonglong2 b, u64 w2, u64 om2) {
    ulonglong2 r;
    r.x = mul2(a.x, om2); fma2(r.x, b.x, w2);
    r.y = mul2(a.y, om2); fma2(r.y, b.y, w2);
    return r;
}

// [B, C, ZYX] -> [B, ZYX, C]
__global__ void transpose_kernel(const float* __restrict__ in) {
    __shared__ float tile[32][33];
    int b = blockIdx.z, s0 = blockIdx.x * 32, c0 = blockIdx.y * 32;
    const float* ib = in   + (size_t)b * CCH * ZYX;
    float*       ob = g_ct + (size_t)b * ZYX * CCH;
    int tx = threadIdx.x, ty = threadIdx.y;
#pragma unroll
    for (int j = 0; j < 32; j += 8)
        tile[ty + j][tx] = ib[(size_t)(c0 + ty + j) * ZYX + s0 + tx];
    __syncthreads();
#pragma unroll
    for (int j = 0; j < 32; j += 8)
        ob[(size_t)(s0 + ty + j) * CCH + c0 + tx] = tile[tx][ty + j];
}

// Phase 1 for one point: trilinear gather (+feats store), feats@Wh1, h@Wh2.
// Produces hl[32] (leaky hidden state) and xw[3]. All static indexing inside.
__device__ __forceinline__ void phase1(const float* __restrict__ pm, int p,
                                       const float* Wh1s, const float* bh1s,
                                       const float* Wh2s, const float* bh2s,
                                       float* __restrict__ out_feats,
                                       float hl[32], float xw[3])
{
    const float vx = pm[3 * p + 0];
    const float vy = pm[3 * p + 1];
    const float vz = pm[3 * p + 2];

    float ix = src_idx(vx), iy = src_idx(vy), iz = src_idx(vz);
    float fx = floorf(ix), fy = floorf(iy), fz = floorf(iz);
    float wx = ix - fx, wy = iy - fy, wz = iz - fz;
    int x0 = min(max((int)fx, 0), 63); int x1 = min(x0 + 1, 63);
    int y0 = min(max((int)fy, 0), 63); int y1 = min(y0 + 1, 63);
    int z0 = min(max((int)fz, 0), 63); int z1 = min(z0 + 1, 63);

    const int b = p >> 16;
    const float* cb = g_ct + (size_t)b * ZYX * CCH;
    const ulonglong2* q000 = (const ulonglong2*)(cb + (size_t)((z0 * 64 + y0) * 64 + x0) * CCH);
    const ulonglong2* q001 = (const ulonglong2*)(cb + (size_t)((z0 * 64 + y0) * 64 + x1) * CCH);
    const ulonglong2* q010 = (const ulonglong2*)(cb + (size_t)((z0 * 64 + y1) * 64 + x0) * CCH);
    const ulonglong2* q011 = (const ulonglong2*)(cb + (size_t)((z0 * 64 + y1) * 64 + x1) * CCH);
    const ulonglong2* q100 = (const ulonglong2*)(cb + (size_t)((z1 * 64 + y0) * 64 + x0) * CCH);
    const ulonglong2* q101 = (const ulonglong2*)(cb + (size_t)((z1 * 64 + y0) * 64 + x1) * CCH);
    const ulonglong2* q110 = (const ulonglong2*)(cb + (size_t)((z1 * 64 + y1) * 64 + x0) * CCH);
    const ulonglong2* q111 = (const ulonglong2*)(cb + (size_t)((z1 * 64 + y1) * 64 + x1) * CCH);

    const u64 wx2 = pk2(wx), omx2 = pk2(1.0f - wx);
    const u64 wy2 = pk2(wy), omy2 = pk2(1.0f - wy);
    const u64 wz2 = pk2(wz), omz2 = pk2(1.0f - wz);

    u64 h1p[16];
#pragma unroll
    for (int m = 0; m < 16; m++) h1p[m] = 0ULL;

    ulonglong2* fo = (ulonglong2*)(out_feats + (size_t)p * CCH);

#pragma unroll 2
    for (int cc = 0; cc < 32; ++cc) {
        ulonglong2 a000 = q000[cc], a001 = q001[cc];
        ulonglong2 a010 = q010[cc], a011 = q011[cc];
        ulonglong2 a100 = q100[cc], a101 = q101[cc];
        ulonglong2 a110 = q110[cc], a111 = q111[cc];

        ulonglong2 c00 = lerpp(a000, a001, wx2, omx2);
        ulonglong2 c01 = lerpp(a010, a011, wx2, omx2);
        ulonglong2 c10 = lerpp(a100, a101, wx2, omx2);
        ulonglong2 c11 = lerpp(a110, a111, wx2, omx2);
        ulonglong2 c0  = lerpp(c00, c01, wy2, omy2);
        ulonglong2 c1  = lerpp(c10, c11, wy2, omy2);
        ulonglong2 f   = lerpp(c0, c1, wz2, omz2);

        fo[cc] = f;

        float2 f01 = upk2(f.x), f23 = upk2(f.y);
        float fa[4] = { f01.x, f01.y, f23.x, f23.y };
#pragma unroll
        for (int e = 0; e < 4; e++) {
            u64 fc2 = pk2(fa[e]);
            const ulonglong2* wr = (const ulonglong2*)(Wh1s + (cc * 4 + e) * 32);
#pragma unroll
            for (int m = 0; m < 8; m++) {
                ulonglong2 w = wr[m];
                fma2(h1p[2 * m],     w.x, fc2);
                fma2(h1p[2 * m + 1], w.y, fc2);
            }
        }
    }

    float h1[32];
#pragma unroll
    for (int m = 0; m < 16; m++) {
        float2 v = upk2(h1p[m]);
        h1[2 * m]     = leakyf(v.x + bh1s[2 * m]);
        h1[2 * m + 1] = leakyf(v.y + bh1s[2 * m + 1]);
    }

    u64 h2p[16];
#pragma unroll
    for (int m = 0; m < 16; m++) h2p[m] = 0ULL;
#pragma unroll
    for (int k = 0; k < 32; k++) {
        u64 hk2 = pk2(h1[k]);
        const ulonglong2* wr = (const ulonglong2*)(Wh2s + k * 32);
#pragma unroll
        for (int m = 0; m < 8; m++) {
            ulonglong2 w = wr[m];
            fma2(h2p[2 * m],     w.x, hk2);
            fma2(h2p[2 * m + 1], w.y, hk2);
        }
    }

#pragma unroll
    for (int m = 0; m < 16; m++) {
        float2 v = upk2(h2p[m]);
        hl[2 * m]     = leakyf(v.x + bh2s[2 * m]);
        hl[2 * m + 1] = leakyf(v.y + bh2s[2 * m + 1]);
    }

    xw[0] = vx - truncf(vx) - 0.5f;
    xw[1] = vy - truncf(vy) - 0.5f;
    xw[2] = vz - truncf(vz) - 0.5f;
}

__global__ __launch_bounds__(BLOCK, 1)
void fused_decoder_kernel(const float* __restrict__ pm,
                          const float* __restrict__ Wh1,
                          const float* __restrict__ bh1,
                          const float* __restrict__ Wh2,
                          const float* __restrict__ bh2,
                          const float* __restrict__ Wh3,
                          const float* __restrict__ bh3,
                          float* __restrict__ out_scalar,
                          float* __restrict__ out_feats)
{
    extern __shared__ float sm[];
    float* Wh3s = sm;                    // 32*WSTRIDE
    float* Wh1s = Wh3s + 32 * WSTRIDE;   // 4096
    float* Wh2s = Wh1s + 4096;           // 1024
    float* bh3s = Wh2s + 1024;           // WSTRIDE
    float* bh1s = bh3s + WSTRIDE;        // 32
    float* bh2s = bh1s + 32;             // 32

    const int tid = threadIdx.x;

    for (int i = tid; i < 32 * TP; i += BLOCK) {
        int k = i / TP, c = i - k * TP;
        Wh3s[k * WSTRIDE + c] = Wh3[i];
    }
    for (int i = tid; i < 4096; i += BLOCK) Wh1s[i] = Wh1[i];
    for (int i = tid; i < 1024; i += BLOCK) Wh2s[i] = Wh2[i];
    for (int i = tid; i < TP;   i += BLOCK) bh3s[i] = bh3[i];
    if (tid < 32) { bh1s[tid] = bh1[tid]; bh2s[tid] = bh2[tid]; }
    __syncthreads();

    const int t0 = blockIdx.x * BLOCK + tid;  // grid 128 * 256 = 32768 threads

#pragma unroll 1
    for (int rep = 0; rep < 2; rep++) {
        const int pA = t0 + rep * 32768;   // batch 0 point
        const int pB = pA + 65536;         // batch 1 point

        float hlA[32], xwA[3];
        float hlB[32], xwB[3];
        phase1(pm, pA, Wh1s, bh1s, Wh2s, bh2s, out_feats, hlA, xwA);
        phase1(pm, pB, Wh1s, bh1s, Wh2s, bh2s, out_feats, hlB, xwB);

        // ---- generated MLP layer 1 (joint over the pair)
        u64 o1A[16], o1B[16];
        {
            const u64 x0A = pk2(xwA[0]), x1A = pk2(xwA[1]), x2A = pk2(xwA[2]);
            const u64 x0B = pk2(xwB[0]), x1B = pk2(xwB[1]), x2B = pk2(xwB[2]);
#pragma unroll
            for (int m = 0; m < 8; m++) {
                ulonglong2 b0 = ((const ulonglong2*)(bh3s +  0))[m];
                ulonglong2 b1 = ((const ulonglong2*)(bh3s + 32))[m];
                ulonglong2 b2 = ((const ulonglong2*)(bh3s + 64))[m];
                ulonglong2 b3 = ((const ulonglong2*)(bh3s + 96))[m];
                u64 rA0 = mul2(b0.x, x0A); fma2(rA0, b1.x, x1A); fma2(rA0, b2.x, x2A);
                u64 rA1 = mul2(b0.y, x0A); fma2(rA1, b1.y, x1A); fma2(rA1, b2.y, x2A);
                o1A[2*m]   = add2(rA0, b3.x);
                o1A[2*m+1] = add2(rA1, b3.y);
                u64 rB0 = mul2(b0.x, x0B); fma2(rB0, b1.x, x1B); fma2(rB0, b2.x, x2B);
                u64 rB1 = mul2(b0.y, x0B); fma2(rB1, b1.y, x1B); fma2(rB1, b2.y, x2B);
                o1B[2*m]   = add2(rB0, b3.x);
                o1B[2*m+1] = add2(rB1, b3.y);
            }
#pragma unroll 1
            for (int k = 0; k < 32; k++) {
                float hA = hlA[k], hB = hlB[k];
                u64 t0A = pk2(hA * xwA[0]), t1A = pk2(hA * xwA[1]), t2A = pk2(hA * xwA[2]), hA2 = pk2(hA);
                u64 t0B = pk2(hB * xwB[0]), t1B = pk2(hB * xwB[1]), t2B = pk2(hB * xwB[2]), hB2 = pk2(hB);
                const float* wr = Wh3s + k * WSTRIDE;
#pragma unroll
                for (int m = 0; m < 8; m++) {
                    ulonglong2 w0 = ((const ulonglong2*)(wr +  0))[m];
                    ulonglong2 w1 = ((const ulonglong2*)(wr + 32))[m];
                    ulonglong2 w2 = ((const ulonglong2*)(wr + 64))[m];
                    ulonglong2 w3 = ((const ulonglong2*)(wr + 96))[m];
                    u64 aA0 = o1A[2*m], aA1 = o1A[2*m+1];
                    fma2(aA0, w0.x, t0A); fma2(aA1, w0.y, t0A);
                    fma2(aA0, w1.x, t1A); fma2(aA1, w1.y, t1A);
                    fma2(aA0, w2.x, t2A); fma2(aA1, w2.y, t2A);
                    fma2(aA0, w3.x, hA2); fma2(aA1, w3.y, hA2);
                    o1A[2*m] = aA0; o1A[2*m+1] = aA1;
                    u64 aB0 = o1B[2*m], aB1 = o1B[2*m+1];
                    fma2(aB0, w0.x, t0B); fma2(aB1, w0.y, t0B);
                    fma2(aB0, w1.x, t1B); fma2(aB1, w1.y, t1B);
                    fma2(aB0, w2.x, t2B); fma2(aB1, w2.y, t2B);
                    fma2(aB0, w3.x, hB2); fma2(aB1, w3.y, hB2);
                    o1B[2*m] = aB0; o1B[2*m+1] = aB1;
                }
            }
        }

        // activations in REGISTERS (statically indexed everywhere below)
        float aA[33], aB[33];
#pragma unroll
        for (int m = 0; m < 16; m++) {
            float2 vA = upk2(o1A[m]);
            aA[2*m] = leakyf(vA.x); aA[2*m+1] = leakyf(vA.y);
            float2 vB = upk2(o1B[m]);
            aB[2*m] = leakyf(vB.x); aB[2*m+1] = leakyf(vB.y);
        }
        aA[32] = 1.0f; aB[32] = 1.0f;

        // ---- layer 2: bias part (i unrolled; weights shared across pair)
        u64 o2A[16], o2B[16];
#pragma unroll
        for (int m = 0; m < 16; m++) { o2A[m] = 0ULL; o2B[m] = 0ULL; }
#pragma unroll
        for (int i = 0; i < 33; i++) {
            u64 aiA = pk2(aA[i]);
            u64 aiB = pk2(aB[i]);
            const ulonglong2* br = (const ulonglong2*)(bh3s + 128 + i * 32);
#pragma unroll
            for (int m = 0; m < 8; m++) {
                ulonglong2 w = br[m];
                fma2(o2A[2*m], w.x, aiA); fma2(o2A[2*m+1], w.y, aiA);
                fma2(o2B[2*m], w.x, aiB); fma2(o2B[2*m+1], w.y, aiB);
            }
        }
        // ---- layer 2: main contraction (dominant loop; 8 LDS -> 32 fma2)
#pragma unroll 1
        for (int k = 0; k < 32; k++) {
            const float hA = hlA[k], hB = hlB[k];
            const float* wr = Wh3s + k * WSTRIDE + 128;
#pragma unroll
            for (int i = 0; i < 33; i++) {
                u64 tA = pk2(hA * aA[i]);
                u64 tB = pk2(hB * aB[i]);
                const ulonglong2* w4 = (const ulonglong2*)(wr + i * 32);
#pragma unroll
                for (int m = 0; m < 8; m++) {
                    ulonglong2 w = w4[m];
                    fma2(o2A[2*m], w.x, tA); fma2(o2A[2*m+1], w.y, tA);
                    fma2(o2B[2*m], w.x, tB); fma2(o2B[2*m+1], w.y, tB);
                }
            }
        }

        float a2A[32], a2B[32];
#pragma unroll
        for (int m = 0; m < 16; m++) {
            float2 vA = upk2(o2A[m]);
            a2A[2*m] = leakyf(vA.x); a2A[2*m+1] = leakyf(vA.y);
            float2 vB = upk2(o2B[m]);
            a2B[2*m] = leakyf(vB.x); a2B[2*m+1] = leakyf(vB.y);
        }

        // ---- layer 3 (cols 1184..1215 = W3, col 1216 = b3), joint
        u64 w3A[16], w3B[16];
#pragma unroll
        for (int m = 0; m < 16; m++) { w3A[m] = 0ULL; w3B[m] = 0ULL; }
        float w3bA = 0.0f, w3bB = 0.0f;
#pragma unroll 1
        for (int k = 0; k < 32; k++) {
            float hA = hlA[k], hB = hlB[k];
            u64 hA2 = pk2(hA), hB2 = pk2(hB);
            const float* wr = Wh3s + k * WSTRIDE + 1184;
#pragma unroll
            for (int m = 0; m < 8; m++) {
                ulonglong2 w = ((const ulonglong2*)wr)[m];
                fma2(w3A[2*m], w.x, hA2); fma2(w3A[2*m+1], w.y, hA2);
                fma2(w3B[2*m], w.x, hB2); fma2(w3B[2*m+1], w.y, hB2);
            }
            w3bA += hA * wr[32];
            w3bB += hB * wr[32];
        }

        float accA = w3bA + bh3s[1216];
        float accB = w3bB + bh3s[1216];
#pragma unroll
        for (int m = 0; m < 16; m++) {
            float2 vA = upk2(w3A[m]);
            accA += a2A[2*m]   * (vA.x + bh3s[1184 + 2*m]);
            accA += a2A[2*m+1] * (vA.y + bh3s[1184 + 2*m + 1]);
            float2 vB = upk2(w3B[m]);
            accB += a2B[2*m]   * (vB.x + bh3s[1184 + 2*m]);
            accB += a2B[2*m+1] * (vB.y + bh3s[1184 + 2*m + 1]);
        }

        out_scalar[pA] = accA;
        out_scalar[pB] = accB;
    }
}

extern "C" void kernel_launch(void* const* d_in, const int* in_sizes, int n_in,
                              void* d_out, int out_size)
{
    (void)in_sizes; (void)n_in; (void)out_size;
    // inputs: 0 pcl (unused), 1 pcl_mem, 2 c_plane, 3 Wh1, 4 bh1, 5 Wh2, 6 bh2, 7 Wh3, 8 bh3
    const float* pcl_mem = (const float*)d_in[1];
    const float* c_plane = (const float*)d_in[2];
    const float* Wh1 = (const float*)d_in[3];
    const float* bh1 = (const float*)d_in[4];
    const float* Wh2 = (const float*)d_in[5];
    const float* bh2 = (const float*)d_in[6];
    const float* Wh3 = (const float*)d_in[7];
    const float* bh3 = (const float*)d_in[8];

    float* out   = (float*)d_out;            // [B*N] scalar out first
    float* feats = out + (size_t)BB * NN;    // then [B*N*128] feats

    dim3 tg(ZYX / 32, CCH / 32, BB);
    transpose_kernel<<<tg, dim3(32, 8, 1)>>>(c_plane);

    size_t smem = (size_t)(32 * WSTRIDE + 4096 + 1024 + WSTRIDE + 32 + 32) * sizeof(float);
    cudaFuncSetAttribute(fused_decoder_kernel,
                         cudaFuncAttributeMaxDynamicSharedMemorySize, (int)smem);
    // 128 CTAs * 256 threads = 32768 threads; each handles exactly 2 pairs (4 points)
    fused_decoder_kernel<<<128, BLOCK, smem>>>(pcl_mem, Wh1, bh1, Wh2, bh2,
                                               Wh3, bh3, out, feats);
}

// round 8
// speedup vs baseline: 1.1936x; 1.0114x over previous
#include <cuda_runtime.h>

#define BB 2
#define NN 65536
#define CCH 128
#define ZYX (64*64*64)
#define TP 1217
#define WSTRIDE 1220
#define BLOCK 320
#define NPTS (BB * NN)

typedef unsigned long long u64;

__device__ float g_ct[(size_t)BB * ZYX * CCH]; // c_plane transposed to [B, ZYX, C]

__device__ __forceinline__ float leakyf(float v) { return v >= 0.0f ? v : 0.01f * v; }

__device__ __forceinline__ float src_idx(float v) {
    float g = fminf(fmaxf((2.0f * v) / 63.0f - 1.0f, -2.0f), 2.0f);
    return fminf(fmaxf((g + 1.0f) * 0.5f * 63.0f, 0.0f), 63.0f);
}

// ---- packed f32x2 helpers (sm_100+) ----
__device__ __forceinline__ u64 pk2(float v) {
    u64 r; asm("mov.b64 %0, {%1, %1};" : "=l"(r) : "f"(v)); return r;
}
__device__ __forceinline__ void fma2(u64 &d, u64 a, u64 b) {
    asm("fma.rn.f32x2 %0, %1, %2, %0;" : "+l"(d) : "l"(a), "l"(b));
}
__device__ __forceinline__ u64 mul2(u64 a, u64 b) {
    u64 r; asm("mul.rn.f32x2 %0, %1, %2;" : "=l"(r) : "l"(a), "l"(b)); return r;
}
__device__ __forceinline__ u64 add2(u64 a, u64 b) {
    u64 r; asm("add.rn.f32x2 %0, %1, %2;" : "=l"(r) : "l"(a), "l"(b)); return r;
}
__device__ __forceinline__ float2 upk2(u64 v) {
    float2 r; asm("mov.b64 {%0, %1}, %2;" : "=f"(r.x), "=f"(r.y) : "l"(v)); return r;
}
__device__ __forceinline__ ulonglong2 lerpp(ulonglong2 a, ulonglong2 b, u64 w2, u64 om2) {
    ulonglong2 r;
    r.x = mul2(a.x, om2); fma2(r.x, b.x, w2);
    r.y = mul2(a.y, om2); fma2(r.y, b.y, w2);
    return r;
}

// [B, C, ZYX] -> [B, ZYX, C]
__global__ void transpose_kernel(const float* __restrict__ in) {
    __shared__ float tile[32][33];
    int b = blockIdx.z, s0 = blockIdx.x * 32, c0 = blockIdx.y * 32;
    const float* ib = in   + (size_t)b * CCH * ZYX;
    float*       ob = g_ct + (size_t)b * ZYX * CCH;
    int tx = threadIdx.x, ty = threadIdx.y;
#pragma unroll
    for (int j = 0; j < 32; j += 8)
        tile[ty + j][tx] = ib[(size_t)(c0 + ty + j) * ZYX + s0 + tx];
    __syncthreads();
#pragma unroll
    for (int j = 0; j < 32; j += 8)
        ob[(size_t)(s0 + ty + j) * CCH + c0 + tx] = tile[tx][ty + j];
}

__global__ __launch_bounds__(BLOCK, 1)
void fused_decoder_kernel(const float* __restrict__ pm,
                          const float* __restrict__ Wh1,
                          const float* __restrict__ bh1,
                          const float* __restrict__ Wh2,
                          const float* __restrict__ bh2,
                          const float* __restrict__ Wh3,
                          const float* __restrict__ bh3,
                          float* __restrict__ out_scalar,
                          float* __restrict__ out_feats)
{
    extern __shared__ float sm[];
    float* Wh3s = sm;                    // 32*WSTRIDE
    float* Wh1s = Wh3s + 32 * WSTRIDE;   // 4096
    float* Wh2s = Wh1s + 4096;           // 1024
    float* bh3s = Wh2s + 1024;           // WSTRIDE
    float* bh1s = bh3s + WSTRIDE;        // 32
    float* bh2s = bh1s + 32;             // 32
    float* als  = bh2s + 32;             // 33*BLOCK

    const int tid = threadIdx.x;

    for (int i = tid; i < 32 * TP; i += BLOCK) {
        int k = i / TP, c = i - k * TP;
        Wh3s[k * WSTRIDE + c] = Wh3[i];
    }
    for (int i = tid; i < 4096; i += BLOCK) Wh1s[i] = Wh1[i];
    for (int i = tid; i < 1024; i += BLOCK) Wh2s[i] = Wh2[i];
    for (int i = tid; i < TP;   i += BLOCK) bh3s[i] = bh3[i];
    if (tid < 32) { bh1s[tid] = bh1[tid]; bh2s[tid] = bh2[tid]; }
    __syncthreads();

    const int stride = gridDim.x * BLOCK;
    for (int p = blockIdx.x * BLOCK + tid; p < NPTS; p += stride) {
        const float vx = pm[3 * p + 0];
        const float vy = pm[3 * p + 1];
        const float vz = pm[3 * p + 2];

        float ix = src_idx(vx), iy = src_idx(vy), iz = src_idx(vz);
        float fx = floorf(ix), fy = floorf(iy), fz = floorf(iz);
        float wx = ix - fx, wy = iy - fy, wz = iz - fz;
        int x0 = min(max((int)fx, 0), 63); int x1 = min(x0 + 1, 63);
        int y0 = min(max((int)fy, 0), 63); int y1 = min(y0 + 1, 63);
        int z0 = min(max((int)fz, 0), 63); int z1 = min(z0 + 1, 63);

        const int b = p >> 16;
        const float* cb = g_ct + (size_t)b * ZYX * CCH;
        const ulonglong2* q000 = (const ulonglong2*)(cb + (size_t)((z0 * 64 + y0) * 64 + x0) * CCH);
        const ulonglong2* q001 = (const ulonglong2*)(cb + (size_t)((z0 * 64 + y0) * 64 + x1) * CCH);
        const ulonglong2* q010 = (const ulonglong2*)(cb + (size_t)((z0 * 64 + y1) * 64 + x0) * CCH);
        const ulonglong2* q011 = (const ulonglong2*)(cb + (size_t)((z0 * 64 + y1) * 64 + x1) * CCH);
        const ulonglong2* q100 = (const ulonglong2*)(cb + (size_t)((z1 * 64 + y0) * 64 + x0) * CCH);
        const ulonglong2* q101 = (const ulonglong2*)(cb + (size_t)((z1 * 64 + y0) * 64 + x1) * CCH);
        const ulonglong2* q110 = (const ulonglong2*)(cb + (size_t)((z1 * 64 + y1) * 64 + x0) * CCH);
        const ulonglong2* q111 = (const ulonglong2*)(cb + (size_t)((z1 * 64 + y1) * 64 + x1) * CCH);

        const u64 wx2 = pk2(wx), omx2 = pk2(1.0f - wx);
        const u64 wy2 = pk2(wy), omy2 = pk2(1.0f - wy);
        const u64 wz2 = pk2(wz), omz2 = pk2(1.0f - wz);

        u64 h1p[16];
#pragma unroll
        for (int m = 0; m < 16; m++) h1p[m] = 0ULL;

        ulonglong2* fo = (ulonglong2*)(out_feats + (size_t)p * CCH);

        // gather + trilinear + feats store + feats@Wh1 (all packed)
#pragma unroll 2
        for (int cc = 0; cc < 32; ++cc) {
            ulonglong2 a000 = q000[cc], a001 = q001[cc];
            ulonglong2 a010 = q010[cc], a011 = q011[cc];
            ulonglong2 a100 = q100[cc], a101 = q101[cc];
            ulonglong2 a110 = q110[cc], a111 = q111[cc];

            ulonglong2 c00 = lerpp(a000, a001, wx2, omx2);
            ulonglong2 c01 = lerpp(a010, a011, wx2, omx2);
            ulonglong2 c10 = lerpp(a100, a101, wx2, omx2);
            ulonglong2 c11 = lerpp(a110, a111, wx2, omx2);
            ulonglong2 c0  = lerpp(c00, c01, wy2, omy2);
            ulonglong2 c1  = lerpp(c10, c11, wy2, omy2);
            ulonglong2 f   = lerpp(c0, c1, wz2, omz2);

            fo[cc] = f;

            float2 f01 = upk2(f.x), f23 = upk2(f.y);
            float fa[4] = { f01.x, f01.y, f23.x, f23.y };
#pragma unroll
            for (int e = 0; e < 4; e++) {
                u64 fc2 = pk2(fa[e]);
                const ulonglong2* wr = (const ulonglong2*)(Wh1s + (cc * 4 + e) * 32);
#pragma unroll
                for (int m = 0; m < 8; m++) {
                    ulonglong2 w = wr[m];
                    fma2(h1p[2 * m],     w.x, fc2);
                    fma2(h1p[2 * m + 1], w.y, fc2);
                }
            }
        }

        float h1[32];
#pragma unroll
        for (int m = 0; m < 16; m++) {
            float2 v = upk2(h1p[m]);
            h1[2 * m]     = leakyf(v.x + bh1s[2 * m]);
            h1[2 * m + 1] = leakyf(v.y + bh1s[2 * m + 1]);
        }

        // h @ Wh2
        u64 h2p[16];
#pragma unroll
        for (int m = 0; m < 16; m++) h2p[m] = 0ULL;
#pragma unroll 4
        for (int k = 0; k < 32; k++) {
            u64 hk2 = pk2(h1[k]);
            const ulonglong2* wr = (const ulonglong2*)(Wh2s + k * 32);
#pragma unroll
            for (int m = 0; m < 8; m++) {
                ulonglong2 w = wr[m];
                fma2(h2p[2 * m],     w.x, hk2);
                fma2(h2p[2 * m + 1], w.y, hk2);
            }
        }

        float hl[32];
#pragma unroll
        for (int m = 0; m < 16; m++) {
            float2 v = upk2(h2p[m]);
            hl[2 * m]     = leakyf(v.x + bh2s[2 * m]);
            hl[2 * m + 1] = leakyf(v.y + bh2s[2 * m + 1]);
        }

        // ---- generated MLP layer 1
        const float xw0 = vx - truncf(vx) - 0.5f;
        const float xw1 = vy - truncf(vy) - 0.5f;
        const float xw2 = vz - truncf(vz) - 0.5f;
        const u64 xw0_2 = pk2(xw0), xw1_2 = pk2(xw1), xw2_2 = pk2(xw2);

        u64 o1p[16];
#pragma unroll
        for (int m = 0; m < 8; m++) {
            ulonglong2 b0 = ((const ulonglong2*)(bh3s +  0))[m];
            ulonglong2 b1 = ((const ulonglong2*)(bh3s + 32))[m];
            ulonglong2 b2 = ((const ulonglong2*)(bh3s + 64))[m];
            ulonglong2 b3 = ((const ulonglong2*)(bh3s + 96))[m];
            u64 r0 = mul2(b0.x, xw0_2); fma2(r0, b1.x, xw1_2); fma2(r0, b2.x, xw2_2);
            u64 r1 = mul2(b0.y, xw0_2); fma2(r1, b1.y, xw1_2); fma2(r1, b2.y, xw2_2);
            o1p[2 * m]     = add2(r0, b3.x);
            o1p[2 * m + 1] = add2(r1, b3.y);
        }
#pragma unroll 2
        for (int k = 0; k < 32; k++) {
            float hk = hl[k];
            u64 t0 = pk2(hk * xw0), t1 = pk2(hk * xw1), t2 = pk2(hk * xw2), hk2 = pk2(hk);
            const float* wr = Wh3s + k * WSTRIDE;
#pragma unroll
            for (int m = 0; m < 8; m++) {
                ulonglong2 w0 = ((const ulonglong2*)(wr +  0))[m];
                ulonglong2 w1 = ((const ulonglong2*)(wr + 32))[m];
                ulonglong2 w2 = ((const ulonglong2*)(wr + 64))[m];
                ulonglong2 w3 = ((const ulonglong2*)(wr + 96))[m];
                u64 a0 = o1p[2 * m], a1 = o1p[2 * m + 1];
                fma2(a0, w0.x, t0); fma2(a1, w0.y, t0);
                fma2(a0, w1.x, t1); fma2(a1, w1.y, t1);
                fma2(a0, w2.x, t2); fma2(a1, w2.y, t2);
                fma2(a0, w3.x, hk2); fma2(a1, w3.y, hk2);
                o1p[2 * m] = a0; o1p[2 * m + 1] = a1;
            }
        }

        // activations to shared (a[32] = 1 folds the b2 term)
#pragma unroll
        for (int m = 0; m < 16; m++) {
            float2 v = upk2(o1p[m]);
            als[(2 * m) * BLOCK + tid]     = leakyf(v.x);
            als[(2 * m + 1) * BLOCK + tid] = leakyf(v.y);
        }
        als[32 * BLOCK + tid] = 1.0f;

        // ---- layer 2: bias part
        u64 o2p[16];
#pragma unroll
        for (int m = 0; m < 16; m++) o2p[m] = 0ULL;
        for (int i = 0; i < 33; i++) {
            u64 ai2 = pk2(als[i * BLOCK + tid]);
            const ulonglong2* br = (const ulonglong2*)(bh3s + 128 + i * 32);
#pragma unroll
            for (int m = 0; m < 8; m++) {
                ulonglong2 w = br[m];
                fma2(o2p[2 * m],     w.x, ai2);
                fma2(o2p[2 * m + 1], w.y, ai2);
            }
        }
        // ---- layer 2: main contraction (dominant loop)
        for (int i = 0; i < 33; i++) {
            const float ai = als[i * BLOCK + tid];
            const float* base = Wh3s + 128 + i * 32;
#pragma unroll 8
            for (int k = 0; k < 32; k++) {
                u64 t2p = pk2(hl[k] * ai);
                const ulonglong2* w4 = (const ulonglong2*)(base + k * WSTRIDE);
#pragma unroll
                for (int m = 0; m < 8; m++) {
                    ulonglong2 w = w4[m];
                    fma2(o2p[2 * m],     w.x, t2p);
                    fma2(o2p[2 * m + 1], w.y, t2p);
                }
            }
        }

        float a2[32];
#pragma unroll
        for (int m = 0; m < 16; m++) {
            float2 v = upk2(o2p[m]);
            a2[2 * m]     = leakyf(v.x);
            a2[2 * m + 1] = leakyf(v.y);
        }

        // ---- layer 3 (cols 1184..1215 = W3, col 1216 = b3)
        u64 w3p[16];
#pragma unroll
        for (int m = 0; m < 16; m++) w3p[m] = 0ULL;
        float w3b = 0.0f;
#pragma unroll 4
        for (int k = 0; k < 32; k++) {
            float hk = hl[k];
            u64 hk2 = pk2(hk);
            const float* wr = Wh3s + k * WSTRIDE + 1184;
#pragma unroll
            for (int m = 0; m < 8; m++) {
                ulonglong2 w = ((const ulonglong2*)wr)[m];
                fma2(w3p[2 * m],     w.x, hk2);
                fma2(w3p[2 * m + 1], w.y, hk2);
            }
            w3b += hk * wr[32];
        }

        float acc = w3b + bh3s[1216];
#pragma unroll
        for (int m = 0; m < 16; m++) {
            float2 v = upk2(w3p[m]);
            acc += a2[2 * m]     * (v.x + bh3s[1184 + 2 * m]);
            acc += a2[2 * m + 1] * (v.y + bh3s[1184 + 2 * m + 1]);
        }

        out_scalar[p] = acc;
    }
}

extern "C" void kernel_launch(void* const* d_in, const int* in_sizes, int n_in,
                              void* d_out, int out_size)
{
    (void)in_sizes; (void)n_in; (void)out_size;
    // inputs: 0 pcl (unused), 1 pcl_mem, 2 c_plane, 3 Wh1, 4 bh1, 5 Wh2, 6 bh2, 7 Wh3, 8 bh3
    const float* pcl_mem = (const float*)d_in[1];
    const float* c_plane = (const float*)d_in[2];
    const float* Wh1 = (const float*)d_in[3];
    const float* bh1 = (const float*)d_in[4];
    const float* Wh2 = (const float*)d_in[5];
    const float* bh2 = (const float*)d_in[6];
    const float* Wh3 = (const float*)d_in[7];
    const float* bh3 = (const float*)d_in[8];

    float* out   = (float*)d_out;            // [B*N] scalar out first
    float* feats = out + (size_t)BB * NN;    // then [B*N*128] feats

    dim3 tg(ZYX / 32, CCH / 32, BB);
    transpose_kernel<<<tg, dim3(32, 8, 1)>>>(c_plane);

    // smem: 32*1220 + 4096 + 1024 + 1220 + 64 + 33*320 = 56004 floats = 224016 B
    size_t smem = (size_t)(32 * WSTRIDE + 4096 + 1024 + WSTRIDE + 32 + 32 + 33 * BLOCK) * sizeof(float);
    cudaFuncSetAttribute(fused_decoder_kernel,
                         cudaFuncAttributeMaxDynamicSharedMemorySize, (int)smem);
    // persistent: 148 CTAs * 320 threads = 47360 threads, 10 warps/SM
    fused_decoder_kernel<<<148, BLOCK, smem>>>(pcl_mem, Wh1, bh1, Wh2, bh2,
                                               Wh3, bh3, out, feats);
}